// round 14
// baseline (speedup 1.0000x reference)
#include <cuda_runtime.h>
#include <cuda_fp16.h>
#include <cstdint>

#define BATCH 64
#define NNODE 27
#define CDIM  512
#define NNSQ  729
#define NROWS_X (BATCH*NNODE)      // 1728
#define NROWS_E (BATCH*NNSQ)       // 46656
#define SSTR 520

#define BM 128
#define BN 128
#define BK 64
#define SROWB 144                   // smem row stride bytes (64 halves + 16B pad)
#define ARR_BYTES (128*SROWB)       // 18432
#define STAGE_BYTES (2*ARR_BYTES)   // A | B = 36864
#define NSTAGE 3
#define SMEM_GEMM (NSTAGE*STAGE_BYTES)   // 110592 -> 2 CTAs/SM

#define EDGE_CTAS (365*4)           // 1460
#define NODE_CTAS (14*16)           // 224

// epilogue smem layout (floats unless noted)
#define EPI_VIX   (27*SSTR)                 // 14040
#define EPI_GE    (EPI_VIX + 512)
#define EPI_BE    (EPI_GE + 512)
#define EPI_UJX_F (EPI_BE + 512)            // half buffer starts here (float idx)
#define EPI_BYTES (EPI_UJX_F*4 + 27*512*2)  // 62304 + 27648 = 89952

// prep kernel block ranges (256 thr each)
#define PREP_E_BLKS (NROWS_E*CDIM/4/256)   // 23328
#define PREP_X_BLKS (NROWS_X*CDIM/4/256)   // 864
#define PREP_W_BLKS (16*16*5)              // 1280

// ------------------------------------------------------------------
// scratch (device globals; allocs are forbidden)
// ------------------------------------------------------------------
__device__ __half g_elin[(size_t)NROWS_E*CDIM];         // e_lin fp16
__device__ __half g_node[(size_t)NROWS_X*2048];         // Vix|Vjx|Ujx|XU fp16
__device__ __half g_eA[(size_t)NROWS_E*CDIM];           // edge fp16
__device__ __half g_xA[(size_t)NROWS_X*CDIM];           // x fp16
__device__ __half g_WEt[512*512];                       // WE^T fp16
__device__ __half g_Wct[2048*512];                      // [WA|WB|WV|WU]^T fp16

// ------------------------------------------------------------------
// helpers
// ------------------------------------------------------------------
__device__ __forceinline__ uint32_t smem_to_u32(const void* p) {
    uint32_t a;
    asm("{ .reg .u64 t; cvta.to.shared.u64 t, %1; cvt.u32.u64 %0, t; }" : "=r"(a) : "l"(p));
    return a;
}
__device__ __forceinline__ void cp_async16(uint32_t dst, const void* src, bool pred) {
    int sz = pred ? 16 : 0;
    asm volatile("cp.async.cg.shared.global [%0], [%1], 16, %2;"
                 :: "r"(dst), "l"(src), "r"(sz) : "memory");
}
__device__ __forceinline__ void ldsm4(uint32_t& r0, uint32_t& r1, uint32_t& r2, uint32_t& r3,
                                      uint32_t addr) {
    asm volatile("ldmatrix.sync.aligned.m8n8.x4.shared.b16 {%0,%1,%2,%3}, [%4];"
                 : "=r"(r0), "=r"(r1), "=r"(r2), "=r"(r3) : "r"(addr));
}
__device__ __forceinline__ void mma16816(float* c,
                                         uint32_t a0, uint32_t a1, uint32_t a2, uint32_t a3,
                                         uint32_t b0, uint32_t b1) {
    asm volatile("mma.sync.aligned.m16n8k16.row.col.f32.f16.f16.f32 "
                 "{%0,%1,%2,%3},{%4,%5,%6,%7},{%8,%9},{%0,%1,%2,%3};"
                 : "+f"(c[0]), "+f"(c[1]), "+f"(c[2]), "+f"(c[3])
                 : "r"(a0), "r"(a1), "r"(a2), "r"(a3), "r"(b0), "r"(b1));
}
__device__ __forceinline__ float sigmoid_fast(float x) {
    float t;
    asm("tanh.approx.f32 %0, %1;" : "=f"(t) : "f"(0.5f * x));
    return fmaf(t, 0.5f, 0.5f);
}
__device__ __forceinline__ float exp01(float s) {
    float p = fmaf(s, 0.14285714f, 1.f);
    p = fmaf(p*s, 0.16666667f, 1.f);
    p = fmaf(p*s, 0.2f, 1.f);
    p = fmaf(p*s, 0.25f, 1.f);
    p = fmaf(p*s, 0.33333333f, 1.f);
    p = fmaf(p*s, 0.5f, 1.f);
    return fmaf(p, s, 1.f);
}

// ------------------------------------------------------------------
// K_prep: one launch = edge convert | x convert | weight transpose
// ------------------------------------------------------------------
__global__ void prep_all(const float* __restrict__ edge, const float* __restrict__ x,
                         const float* __restrict__ WE, const float* __restrict__ WA,
                         const float* __restrict__ WB, const float* __restrict__ WV,
                         const float* __restrict__ WU)
{
    int blk = blockIdx.x;
    if (blk < PREP_E_BLKS + PREP_X_BLKS) {
        const float* A; __half* O; int i;
        if (blk < PREP_E_BLKS) { A = edge; O = g_eA; i = blk*256 + threadIdx.x; }
        else { A = x; O = g_xA; i = (blk - PREP_E_BLKS)*256 + threadIdx.x; }
        float4 v = ((const float4*)A)[i];
        ((__half2*)O)[2*i]   = __floats2half2_rn(v.x, v.y);
        ((__half2*)O)[2*i+1] = __floats2half2_rn(v.z, v.w);
        return;
    }
    __shared__ float tile[32][33];
    int wblk = blk - PREP_E_BLKS - PREP_X_BLKS;
    int z  = wblk / 256;
    int t2 = wblk % 256;
    int bx = t2 & 15, by = t2 >> 4;
    const float* W = (z == 0) ? WE : (z == 1) ? WA : (z == 2) ? WB : (z == 3) ? WV : WU;
    __half* Oh = (z == 0) ? g_WEt : g_Wct;
    const int nOff = (z == 0) ? 0 : (z - 1) * 512;
    const int k0 = bx * 32, n0 = by * 32;
    const int tx = threadIdx.x & 31, ty = threadIdx.x >> 5;
#pragma unroll
    for (int q = 0; q < 4; q++)
        tile[ty + 8*q][tx] = W[(size_t)(k0 + ty + 8*q)*512 + n0 + tx];
    __syncthreads();
#pragma unroll
    for (int q = 0; q < 4; q++)
        Oh[(size_t)(nOff + n0 + ty + 8*q)*512 + k0 + tx] = __float2half_rn(tile[tx][ty + 8*q]);
}

// ------------------------------------------------------------------
// G: combined fp16 GEMM.  256 thr, 8 warps, warp 32x64,
// CTA 128x128, BK=64, 3-stage, 2 CTAs/SM.  All outputs fp16.
// ------------------------------------------------------------------
__device__ __forceinline__ void load_stage(uint32_t s0, int tid, int row0, int n0, int M, int kt,
    const __half* __restrict__ A, const __half* __restrict__ B)
{
#pragma unroll
    for (int q = 0; q < 4; q++) {
        int idx = tid + q*256;                       // 128 rows x 8 16B-chunks
        int r = idx >> 3, c = idx & 7;
        uint32_t doff = (uint32_t)r*SROWB + (uint32_t)c*16;
        int ar = row0 + r;
        bool av = ar < M;
        size_t agoff = (size_t)(av ? ar : 0)*512 + kt + c*8;
        cp_async16(s0 + doff, A + agoff, av);
        size_t bgoff = (size_t)(n0 + r)*512 + kt + c*8;
        cp_async16(s0 + ARR_BYTES + doff, B + bgoff, true);
    }
    asm volatile("cp.async.commit_group;" ::: "memory");
}

__device__ __forceinline__ void compute_stage(uint32_t s0, int lane, int wm, int wn,
                                              float acc[2][8][4])
{
#pragma unroll
    for (int s = 0; s < 4; s++) {
        uint32_t a[2][4];
#pragma unroll
        for (int f = 0; f < 2; f++) {
            uint32_t ra = s0 + (uint32_t)(wm*32 + f*16 + (lane & 15))*SROWB
                             + (uint32_t)((lane >> 4)*16 + s*32);
            ldsm4(a[f][0], a[f][1], a[f][2], a[f][3], ra);
        }
#pragma unroll
        for (int h = 0; h < 2; h++) {
            uint32_t bh[2][4];
#pragma unroll
            for (int q = 0; q < 2; q++) {
                uint32_t rb = s0 + ARR_BYTES
                    + (uint32_t)(wn*64 + h*32 + q*16 + (lane & 15))*SROWB
                    + (uint32_t)((lane >> 4)*16 + s*32);
                ldsm4(bh[q][0], bh[q][1], bh[q][2], bh[q][3], rb);
            }
#pragma unroll
            for (int f = 0; f < 2; f++)
#pragma unroll
                for (int q = 0; q < 2; q++) {
                    int j = h*4 + q*2;
                    mma16816(acc[f][j],   a[f][0], a[f][1], a[f][2], a[f][3], bh[q][0], bh[q][2]);
                    mma16816(acc[f][j+1], a[f][0], a[f][1], a[f][2], a[f][3], bh[q][1], bh[q][3]);
                }
        }
    }
}

__global__ __launch_bounds__(256, 2)
void gemm_all(const __half* __restrict__ eA, const __half* __restrict__ WEt,
              const __half* __restrict__ xA, const __half* __restrict__ Wct,
              __half* __restrict__ Ce, __half* __restrict__ Cn)
{
    extern __shared__ char smem[];
    const uint32_t sb = smem_to_u32(smem);
    const int tid = threadIdx.x;
    const int lane = tid & 31, wid = tid >> 5;
    const int wm = wid >> 1, wn = wid & 1;

    const bool isEdge = blockIdx.x < EDGE_CTAS;
    const __half *A, *B;
    __half* C; int M, ldC, row0, n0;
    if (isEdge) {
        int bx = blockIdx.x % 365, by = blockIdx.x / 365;
        A = eA; B = WEt; C = Ce; M = NROWS_E; ldC = 512;
        row0 = bx * BM; n0 = by * BN;
    } else {
        int c2 = blockIdx.x - EDGE_CTAS;
        int bx = c2 % 14, by = c2 / 14;
        A = xA; B = Wct; C = Cn; M = NROWS_X; ldC = 2048;
        row0 = bx * BM; n0 = by * BN;
    }

    float acc[2][8][4];
#pragma unroll
    for (int f = 0; f < 2; f++)
#pragma unroll
        for (int j = 0; j < 8; j++)
#pragma unroll
            for (int v = 0; v < 4; v++) acc[f][j][v] = 0.f;

    load_stage(sb,               tid, row0, n0, M, 0,  A, B);
    load_stage(sb + STAGE_BYTES, tid, row0, n0, M, BK, A, B);

    const int NT = 512 / BK;   // 8
    for (int t = 0; t < NT; t++) {
        asm volatile("cp.async.wait_group 1;" ::: "memory");   // load(t) done
        __syncthreads();                                        // buf[(t+2)%3] free
        if (t + 2 < NT)
            load_stage(sb + ((t+2) % NSTAGE)*STAGE_BYTES, tid, row0, n0, M, (t+2)*BK, A, B);
        compute_stage(sb + (t % NSTAGE)*STAGE_BYTES, lane, wm, wn, acc);
    }

    // epilogue: fp16 stores (both branches)
#pragma unroll
    for (int f = 0; f < 2; f++) {
        int rbase = row0 + wm*32 + f*16 + (lane >> 2);
#pragma unroll
        for (int h = 0; h < 2; h++) {
            int r = rbase + h*8;
            if (r < M) {
                __half* dst = C + (size_t)r*ldC + n0 + wn*64 + (lane & 3)*2;
#pragma unroll
                for (int j = 0; j < 8; j++)
                    *(__half2*)&dst[j*8] = __floats2half2_rn(acc[f][j][2*h], acc[f][j][2*h+1]);
            }
        }
    }
}

// ------------------------------------------------------------------
// K_epi: per (b,i) CTA, 512 threads.  Edge pipeline + fused node
// finalize.  Node data fp16; Ujx staged in smem.
// ------------------------------------------------------------------
__global__ __launch_bounds__(512)
void edge_epilogue(const float* __restrict__ x,
                   const float* __restrict__ ge, const float* __restrict__ be,
                   const float* __restrict__ gv, const float* __restrict__ bv,
                   float* __restrict__ edge_out, float* __restrict__ x_out)
{
    extern __shared__ float sm[];
    float* sS   = sm;                 // [27][520]
    float* sVix = sm + EPI_VIX;
    float* sGe  = sm + EPI_GE;
    float* sBe  = sm + EPI_BE;
    __half* sUjx = (__half*)(sm + EPI_UJX_F);   // [27][512] fp16
    __shared__ float rs[16], rs2[16];
    __shared__ float bmean, brstd;

    const int tid = threadIdx.x;
    const int bi  = blockIdx.x;
    const int b   = bi / NNODE;
    const int i   = bi % NNODE;
    const size_t rowBaseE = (size_t)b*NNSQ + (size_t)i*NNODE;
    const __half* eBase  = g_eA + rowBaseE*CDIM;
    const __half* elBase = g_elin + rowBaseE*CDIM;

    {   // Vix / gamma / beta
        const __half* vix = g_node + (size_t)bi*2048;
        sVix[tid] = __half2float(vix[tid]);
        sGe[tid]  = ge[tid];
        sBe[tid]  = be[tid];
    }
    // stage Ujx (27x512 fp16) into smem: 1728 uint4 chunks
#pragma unroll
    for (int l = 0; l < 4; l++) {
        int idx = tid + l*512;
        if (idx < 27*64) {
            int j = idx >> 6, c8 = idx & 63;
            *(uint4*)&sUjx[j*512 + c8*8] =
                *(const uint4*)&g_node[((size_t)b*NNODE + j)*2048 + 1024 + c8*8];
        }
    }
    // load e_lin tile 27x512 fp16 -> sS fp32
#pragma unroll
    for (int l = 0; l < 4; l++) {
        int idx = tid + l*512;
        if (idx < 27*64) {
            int r = idx >> 6, c8 = idx & 63;
            const __half2* src = (const __half2*)(elBase + (size_t)r*512 + c8*8);
            float* d = &sS[r*SSTR + c8*8];
#pragma unroll
            for (int p = 0; p < 4; p++) {
                float2 f = __half22float2(src[p]);
                d[2*p] = f.x; d[2*p+1] = f.y;
            }
        }
    }
    __syncthreads();

    // Phase A: rows (16 warps over 27 rows)
    const int lane = tid & 31, wrp = tid >> 5;
    for (int r = wrp; r < NNODE; r += 16) {
        const __half* vjx = g_node + ((size_t)b*NNODE + r)*2048 + 512;  // Vjx fp16
        float2 v[8]; float s = 0.f, s2 = 0.f;
#pragma unroll
        for (int u = 0; u < 8; u++) {
            int c2 = lane + u*32;
            float2 t = *(float2*)&sS[r*SSTR + 2*c2];
            float2 vi = *(const float2*)&sVix[2*c2];
            float2 vj = __half22float2(*(const __half2*)&vjx[2*c2]);
            t.x += vi.x + vj.x; t.y += vi.y + vj.y;
            v[u] = t;
            s += t.x + t.y; s2 += t.x*t.x + t.y*t.y;
        }
#pragma unroll
        for (int o = 16; o > 0; o >>= 1) {
            s  += __shfl_xor_sync(0xffffffffu, s,  o);
            s2 += __shfl_xor_sync(0xffffffffu, s2, o);
        }
        float mean = s * (1.f/512.f);
        float var  = s2 * (1.f/512.f) - mean*mean;
        float rstd = rsqrtf(var + 1e-5f);
        const __half* eRow = eBase + (size_t)r*CDIM;
        float* oRow = edge_out + (rowBaseE + r)*CDIM;
#pragma unroll
        for (int u = 0; u < 8; u++) {
            int c2 = lane + u*32;
            float2 g = *(const float2*)&sGe[2*c2];
            float2 bb = *(const float2*)&sBe[2*c2];
            float2 e = __half22float2(*(const __half2*)&eRow[2*c2]);
            float lnx = (v[u].x - mean)*rstd*g.x + bb.x;
            float lny = (v[u].y - mean)*rstd*g.y + bb.y;
            float eox = e.x + fmaxf(lnx, 0.f);
            float eoy = e.y + fmaxf(lny, 0.f);
            float2 eo = {eox, eoy};
            *(float2*)&oRow[2*c2] = eo;
            sS[r*SSTR + 2*c2]     = sigmoid_fast(eox);
            sS[r*SSTR + 2*c2 + 1] = sigmoid_fast(eoy);
        }
    }
    __syncthreads();

    // Phase B: one column per thread — softmax over j + gated aggregation
    const int c = tid;
    float aggv;
    {
        float sum = 0.f, a = 0.f;
#pragma unroll
        for (int j = 0; j < NNODE; j++) {
            float ex = exp01(sS[j*SSTR + c]);
            sum += ex;
            a   += ex * __half2float(sUjx[j*512 + c]);
        }
        aggv = a / (sum * (float)NNODE);
    }

    // Phase C (fused node finalize for row bi)
    {
        float t = __half2float(g_node[(size_t)bi*2048 + 1536 + c]) + aggv;   // XU + agg
        float s = t, s2 = t*t;
#pragma unroll
        for (int o = 16; o > 0; o >>= 1) {
            s  += __shfl_xor_sync(0xffffffffu, s,  o);
            s2 += __shfl_xor_sync(0xffffffffu, s2, o);
        }
        if (lane == 0) { rs[wrp] = s; rs2[wrp] = s2; }
        __syncthreads();
        if (tid == 0) {
            float S = 0.f, S2 = 0.f;
#pragma unroll
            for (int k = 0; k < 16; k++) { S += rs[k]; S2 += rs2[k]; }
            float mean = S * (1.f/512.f);
            float var  = S2 * (1.f/512.f) - mean*mean;
            bmean = mean; brstd = rsqrtf(var + 1e-5f);
        }
        __syncthreads();
        float ln = (t - bmean)*brstd*gv[c] + bv[c];
        x_out[(size_t)bi*CDIM + c] = fmaxf(x[(size_t)bi*CDIM + c] + ln, 0.f);
    }
}

// ------------------------------------------------------------------
extern "C" void kernel_launch(void* const* d_in, const int* in_sizes, int n_in,
                              void* d_out, int out_size)
{
    const float* x    = (const float*)d_in[0];
    const float* edge = (const float*)d_in[1];
    const float* WA   = (const float*)d_in[2];
    const float* WB   = (const float*)d_in[3];
    const float* WE   = (const float*)d_in[4];
    const float* WU   = (const float*)d_in[5];
    const float* WV   = (const float*)d_in[6];
    const float* gv   = (const float*)d_in[7];
    const float* bv   = (const float*)d_in[8];
    const float* ge   = (const float*)d_in[9];
    const float* be   = (const float*)d_in[10];

    float* x_out = (float*)d_out;
    float* e_out = (float*)d_out + (size_t)NROWS_X*CDIM;

    cudaFuncSetAttribute(gemm_all, cudaFuncAttributeMaxDynamicSharedMemorySize, SMEM_GEMM);
    cudaFuncSetAttribute(edge_epilogue, cudaFuncAttributeMaxDynamicSharedMemorySize, EPI_BYTES);

    __half *d_elin, *d_node, *d_eA, *d_xA, *d_WEt, *d_Wct;
    cudaGetSymbolAddress((void**)&d_elin, g_elin);
    cudaGetSymbolAddress((void**)&d_node, g_node);
    cudaGetSymbolAddress((void**)&d_eA, g_eA);
    cudaGetSymbolAddress((void**)&d_xA, g_xA);
    cudaGetSymbolAddress((void**)&d_WEt, g_WEt);
    cudaGetSymbolAddress((void**)&d_Wct, g_Wct);

    prep_all<<<PREP_E_BLKS + PREP_X_BLKS + PREP_W_BLKS, 256>>>(edge, x, WE, WA, WB, WV, WU);

    gemm_all<<<EDGE_CTAS + NODE_CTAS, 256, SMEM_GEMM>>>(
        d_eA, d_WEt, d_xA, d_Wct, d_elin, d_node);

    edge_epilogue<<<BATCH*NNODE, 512, EPI_BYTES>>>(
        x, ge, be, gv, bv, e_out, x_out);
}

// round 15
// speedup vs baseline: 1.1553x; 1.1553x over previous
#include <cuda_runtime.h>
#include <cuda_fp16.h>
#include <cstdint>

#define BATCH 64
#define NNODE 27
#define CDIM  512
#define NNSQ  729
#define NROWS_X (BATCH*NNODE)      // 1728
#define NROWS_E (BATCH*NNSQ)       // 46656
#define SSTR 520

#define BM 128
#define BN 128
#define BK 64
#define SROWB 144                   // smem row stride bytes (64 halves + 16B pad)
#define ARR_BYTES (128*SROWB)       // 18432
#define STAGE_BYTES (2*ARR_BYTES)   // A | B = 36864
#define NSTAGE 2
#define SMEM_GEMM (NSTAGE*STAGE_BYTES)   // 73728 -> 2 CTAs/SM

#define EDGE_CTAS (365*4)           // 1460
#define NODE_CTAS (14*16)           // 224

#define EPI_BYTES ((27*SSTR + 1536) * 4)   // 62304 -> 3 CTAs/SM

// prep kernel block ranges (256 thr each)
#define PREP_E_BLKS (NROWS_E*CDIM/8/256)   // 11664 (2 float4 per thread)
#define PREP_X_BLKS (NROWS_X*CDIM/4/256)   // 864
#define PREP_W_BLKS (16*16*5)              // 1280

// ------------------------------------------------------------------
// scratch (device globals; allocs are forbidden)
// ------------------------------------------------------------------
__device__ __half g_elin[(size_t)NROWS_E*CDIM];         // e_lin fp16
__device__ __half g_node[(size_t)NROWS_X*2048];         // Vix|Vjx|Ujx|XU fp16
__device__ __half g_eA[(size_t)NROWS_E*CDIM];           // edge fp16
__device__ __half g_xA[(size_t)NROWS_X*CDIM];           // x fp16
__device__ __half g_WEt[512*512];                       // WE^T fp16
__device__ __half g_Wct[2048*512];                      // [WA|WB|WV|WU]^T fp16

// ------------------------------------------------------------------
// helpers
// ------------------------------------------------------------------
__device__ __forceinline__ uint32_t smem_to_u32(const void* p) {
    uint32_t a;
    asm("{ .reg .u64 t; cvta.to.shared.u64 t, %1; cvt.u32.u64 %0, t; }" : "=r"(a) : "l"(p));
    return a;
}
__device__ __forceinline__ void cp_async16(uint32_t dst, const void* src, bool pred) {
    int sz = pred ? 16 : 0;
    asm volatile("cp.async.cg.shared.global [%0], [%1], 16, %2;"
                 :: "r"(dst), "l"(src), "r"(sz) : "memory");
}
__device__ __forceinline__ void ldsm4(uint32_t& r0, uint32_t& r1, uint32_t& r2, uint32_t& r3,
                                      uint32_t addr) {
    asm volatile("ldmatrix.sync.aligned.m8n8.x4.shared.b16 {%0,%1,%2,%3}, [%4];"
                 : "=r"(r0), "=r"(r1), "=r"(r2), "=r"(r3) : "r"(addr));
}
__device__ __forceinline__ void mma16816(float* c,
                                         uint32_t a0, uint32_t a1, uint32_t a2, uint32_t a3,
                                         uint32_t b0, uint32_t b1) {
    asm volatile("mma.sync.aligned.m16n8k16.row.col.f32.f16.f16.f32 "
                 "{%0,%1,%2,%3},{%4,%5,%6,%7},{%8,%9},{%0,%1,%2,%3};"
                 : "+f"(c[0]), "+f"(c[1]), "+f"(c[2]), "+f"(c[3])
                 : "r"(a0), "r"(a1), "r"(a2), "r"(a3), "r"(b0), "r"(b1));
}
__device__ __forceinline__ float sigmoid_fast(float x) {
    float t;
    asm("tanh.approx.f32 %0, %1;" : "=f"(t) : "f"(0.5f * x));
    return fmaf(t, 0.5f, 0.5f);
}
__device__ __forceinline__ float exp01(float s) {
    float p = fmaf(s, 0.14285714f, 1.f);
    p = fmaf(p*s, 0.16666667f, 1.f);
    p = fmaf(p*s, 0.2f, 1.f);
    p = fmaf(p*s, 0.25f, 1.f);
    p = fmaf(p*s, 0.33333333f, 1.f);
    p = fmaf(p*s, 0.5f, 1.f);
    return fmaf(p, s, 1.f);
}

// ------------------------------------------------------------------
// K_prep: one launch = edge convert (2xfloat4/thr) | x convert | W^T
// ------------------------------------------------------------------
__global__ void prep_all(const float* __restrict__ edge, const float* __restrict__ x,
                         const float* __restrict__ WE, const float* __restrict__ WA,
                         const float* __restrict__ WB, const float* __restrict__ WV,
                         const float* __restrict__ WU)
{
    int blk = blockIdx.x;
    if (blk < PREP_E_BLKS) {                 // edge: 2 float4 per thread
        int i = (blk*256 + threadIdx.x)*2;
#pragma unroll
        for (int u = 0; u < 2; u++) {
            float4 v = ((const float4*)edge)[i + u];
            ((__half2*)g_eA)[2*(i+u)]   = __floats2half2_rn(v.x, v.y);
            ((__half2*)g_eA)[2*(i+u)+1] = __floats2half2_rn(v.z, v.w);
        }
        return;
    }
    if (blk < PREP_E_BLKS + PREP_X_BLKS) {   // x: 1 float4 per thread
        int i = (blk - PREP_E_BLKS)*256 + threadIdx.x;
        float4 v = ((const float4*)x)[i];
        ((__half2*)g_xA)[2*i]   = __floats2half2_rn(v.x, v.y);
        ((__half2*)g_xA)[2*i+1] = __floats2half2_rn(v.z, v.w);
        return;
    }
    __shared__ float tile[32][33];
    int wblk = blk - PREP_E_BLKS - PREP_X_BLKS;
    int z  = wblk / 256;
    int t2 = wblk % 256;
    int bx = t2 & 15, by = t2 >> 4;
    const float* W = (z == 0) ? WE : (z == 1) ? WA : (z == 2) ? WB : (z == 3) ? WV : WU;
    __half* Oh = (z == 0) ? g_WEt : g_Wct;
    const int nOff = (z == 0) ? 0 : (z - 1) * 512;
    const int k0 = bx * 32, n0 = by * 32;
    const int tx = threadIdx.x & 31, ty = threadIdx.x >> 5;
#pragma unroll
    for (int q = 0; q < 4; q++)
        tile[ty + 8*q][tx] = W[(size_t)(k0 + ty + 8*q)*512 + n0 + tx];
    __syncthreads();
#pragma unroll
    for (int q = 0; q < 4; q++)
        Oh[(size_t)(nOff + n0 + ty + 8*q)*512 + k0 + tx] = __float2half_rn(tile[tx][ty + 8*q]);
}

// ------------------------------------------------------------------
// G: combined fp16 GEMM.  256 thr, 8 warps, warp 32x64,
// CTA 128x128, BK=64, 2-stage, 2 CTAs/SM.  All outputs fp16.
// ------------------------------------------------------------------
__device__ __forceinline__ void load_stage(uint32_t s0, int tid, int row0, int n0, int M, int kt,
    const __half* __restrict__ A, const __half* __restrict__ B)
{
#pragma unroll
    for (int q = 0; q < 4; q++) {
        int idx = tid + q*256;                       // 128 rows x 8 16B-chunks
        int r = idx >> 3, c = idx & 7;
        uint32_t doff = (uint32_t)r*SROWB + (uint32_t)c*16;
        int ar = row0 + r;
        bool av = ar < M;
        size_t agoff = (size_t)(av ? ar : 0)*512 + kt + c*8;
        cp_async16(s0 + doff, A + agoff, av);
        size_t bgoff = (size_t)(n0 + r)*512 + kt + c*8;
        cp_async16(s0 + ARR_BYTES + doff, B + bgoff, true);
    }
    asm volatile("cp.async.commit_group;" ::: "memory");
}

__device__ __forceinline__ void compute_stage(uint32_t s0, int lane, int wm, int wn,
                                              float acc[2][8][4])
{
#pragma unroll
    for (int s = 0; s < 4; s++) {
        uint32_t a[2][4];
#pragma unroll
        for (int f = 0; f < 2; f++) {
            uint32_t ra = s0 + (uint32_t)(wm*32 + f*16 + (lane & 15))*SROWB
                             + (uint32_t)((lane >> 4)*16 + s*32);
            ldsm4(a[f][0], a[f][1], a[f][2], a[f][3], ra);
        }
#pragma unroll
        for (int h = 0; h < 2; h++) {
            uint32_t bh[2][4];
#pragma unroll
            for (int q = 0; q < 2; q++) {
                uint32_t rb = s0 + ARR_BYTES
                    + (uint32_t)(wn*64 + h*32 + q*16 + (lane & 15))*SROWB
                    + (uint32_t)((lane >> 4)*16 + s*32);
                ldsm4(bh[q][0], bh[q][1], bh[q][2], bh[q][3], rb);
            }
#pragma unroll
            for (int f = 0; f < 2; f++)
#pragma unroll
                for (int q = 0; q < 2; q++) {
                    int j = h*4 + q*2;
                    mma16816(acc[f][j],   a[f][0], a[f][1], a[f][2], a[f][3], bh[q][0], bh[q][2]);
                    mma16816(acc[f][j+1], a[f][0], a[f][1], a[f][2], a[f][3], bh[q][1], bh[q][3]);
                }
        }
    }
}

__global__ __launch_bounds__(256, 2)
void gemm_all(const __half* __restrict__ eA, const __half* __restrict__ WEt,
              const __half* __restrict__ xA, const __half* __restrict__ Wct,
              __half* __restrict__ Ce, __half* __restrict__ Cn)
{
    extern __shared__ char smem[];
    const uint32_t sb = smem_to_u32(smem);
    const int tid = threadIdx.x;
    const int lane = tid & 31, wid = tid >> 5;
    const int wm = wid >> 1, wn = wid & 1;

    const bool isEdge = blockIdx.x < EDGE_CTAS;
    const __half *A, *B;
    __half* C; int M, ldC, row0, n0;
    if (isEdge) {
        int bx = blockIdx.x % 365, by = blockIdx.x / 365;
        A = eA; B = WEt; C = Ce; M = NROWS_E; ldC = 512;
        row0 = bx * BM; n0 = by * BN;
    } else {
        int c2 = blockIdx.x - EDGE_CTAS;
        int bx = c2 % 14, by = c2 / 14;
        A = xA; B = Wct; C = Cn; M = NROWS_X; ldC = 2048;
        row0 = bx * BM; n0 = by * BN;
    }

    float acc[2][8][4];
#pragma unroll
    for (int f = 0; f < 2; f++)
#pragma unroll
        for (int j = 0; j < 8; j++)
#pragma unroll
            for (int v = 0; v < 4; v++) acc[f][j][v] = 0.f;

    load_stage(sb, tid, row0, n0, M, 0, A, B);

    const int NT = 512 / BK;   // 8
    for (int t = 0; t < NT; t++) {
        asm volatile("cp.async.wait_group 0;" ::: "memory");   // load(t) done
        __syncthreads();                                        // buf[(t+1)&1] free
        if (t + 1 < NT)
            load_stage(sb + ((t+1) & 1)*STAGE_BYTES, tid, row0, n0, M, (t+1)*BK, A, B);
        compute_stage(sb + (t & 1)*STAGE_BYTES, lane, wm, wn, acc);
    }

    // epilogue: fp16 stores (both branches)
#pragma unroll
    for (int f = 0; f < 2; f++) {
        int rbase = row0 + wm*32 + f*16 + (lane >> 2);
#pragma unroll
        for (int h = 0; h < 2; h++) {
            int r = rbase + h*8;
            if (r < M) {
                __half* dst = C + (size_t)r*ldC + n0 + wn*64 + (lane & 3)*2;
#pragma unroll
                for (int j = 0; j < 8; j++)
                    *(__half2*)&dst[j*8] = __floats2half2_rn(acc[f][j][2*h], acc[f][j][2*h+1]);
            }
        }
    }
}

// ------------------------------------------------------------------
// K_epi: per (b,i) CTA, 512 threads, 62.3 KB smem (3 CTAs/SM).
// Edge pipeline + fused node finalize.  Node data fp16 (direct L2).
// ------------------------------------------------------------------
__global__ __launch_bounds__(512)
void edge_epilogue(const float* __restrict__ x,
                   const float* __restrict__ ge, const float* __restrict__ be,
                   const float* __restrict__ gv, const float* __restrict__ bv,
                   float* __restrict__ edge_out, float* __restrict__ x_out)
{
    extern __shared__ float sm[];
    float* sS   = sm;                 // [27][520]
    float* sVix = sm + 27*SSTR;
    float* sGe  = sVix + 512;
    float* sBe  = sGe + 512;
    __shared__ float rs[16], rs2[16];
    __shared__ float bmean, brstd;

    const int tid = threadIdx.x;
    const int bi  = blockIdx.x;
    const int b   = bi / NNODE;
    const int i   = bi % NNODE;
    const size_t rowBaseE = (size_t)b*NNSQ + (size_t)i*NNODE;
    const __half* eBase  = g_eA + rowBaseE*CDIM;
    const __half* elBase = g_elin + rowBaseE*CDIM;

    {   // Vix / gamma / beta
        const __half* vix = g_node + (size_t)bi*2048;
        sVix[tid] = __half2float(vix[tid]);
        sGe[tid]  = ge[tid];
        sBe[tid]  = be[tid];
    }
    // load e_lin tile 27x512 fp16 -> sS fp32
#pragma unroll
    for (int l = 0; l < 4; l++) {
        int idx = tid + l*512;
        if (idx < 27*64) {
            int r = idx >> 6, c8 = idx & 63;
            const __half2* src = (const __half2*)(elBase + (size_t)r*512 + c8*8);
            float* d = &sS[r*SSTR + c8*8];
#pragma unroll
            for (int p = 0; p < 4; p++) {
                float2 f = __half22float2(src[p]);
                d[2*p] = f.x; d[2*p+1] = f.y;
            }
        }
    }
    __syncthreads();

    // Phase A: rows (16 warps over 27 rows)
    const int lane = tid & 31, wrp = tid >> 5;
    for (int r = wrp; r < NNODE; r += 16) {
        const __half* vjx = g_node + ((size_t)b*NNODE + r)*2048 + 512;  // Vjx fp16
        float2 v[8]; float s = 0.f, s2 = 0.f;
#pragma unroll
        for (int u = 0; u < 8; u++) {
            int c2 = lane + u*32;
            float2 t = *(float2*)&sS[r*SSTR + 2*c2];
            float2 vi = *(const float2*)&sVix[2*c2];
            float2 vj = __half22float2(*(const __half2*)&vjx[2*c2]);
            t.x += vi.x + vj.x; t.y += vi.y + vj.y;
            v[u] = t;
            s += t.x + t.y; s2 += t.x*t.x + t.y*t.y;
        }
#pragma unroll
        for (int o = 16; o > 0; o >>= 1) {
            s  += __shfl_xor_sync(0xffffffffu, s,  o);
            s2 += __shfl_xor_sync(0xffffffffu, s2, o);
        }
        float mean = s * (1.f/512.f);
        float var  = s2 * (1.f/512.f) - mean*mean;
        float rstd = rsqrtf(var + 1e-5f);
        const __half* eRow = eBase + (size_t)r*CDIM;
        float* oRow = edge_out + (rowBaseE + r)*CDIM;
#pragma unroll
        for (int u = 0; u < 8; u++) {
            int c2 = lane + u*32;
            float2 g = *(const float2*)&sGe[2*c2];
            float2 bb = *(const float2*)&sBe[2*c2];
            float2 e = __half22float2(*(const __half2*)&eRow[2*c2]);
            float lnx = (v[u].x - mean)*rstd*g.x + bb.x;
            float lny = (v[u].y - mean)*rstd*g.y + bb.y;
            float eox = e.x + fmaxf(lnx, 0.f);
            float eoy = e.y + fmaxf(lny, 0.f);
            float2 eo = {eox, eoy};
            *(float2*)&oRow[2*c2] = eo;
            sS[r*SSTR + 2*c2]     = sigmoid_fast(eox);
            sS[r*SSTR + 2*c2 + 1] = sigmoid_fast(eoy);
        }
    }
    __syncthreads();

    // Phase B: one column per thread — softmax over j + gated aggregation
    const int c = tid;
    float aggv;
    {
        float sum = 0.f, a = 0.f;
#pragma unroll
        for (int j = 0; j < NNODE; j++) {
            float ex = exp01(sS[j*SSTR + c]);
            sum += ex;
            a   += ex * __half2float(g_node[((size_t)b*NNODE + j)*2048 + 1024 + c]);  // Ujx
        }
        aggv = a / (sum * (float)NNODE);
    }

    // Phase C (fused node finalize for row bi)
    {
        float t = __half2float(g_node[(size_t)bi*2048 + 1536 + c]) + aggv;   // XU + agg
        float s = t, s2 = t*t;
#pragma unroll
        for (int o = 16; o > 0; o >>= 1) {
            s  += __shfl_xor_sync(0xffffffffu, s,  o);
            s2 += __shfl_xor_sync(0xffffffffu, s2, o);
        }
        if (lane == 0) { rs[wrp] = s; rs2[wrp] = s2; }
        __syncthreads();
        if (tid == 0) {
            float S = 0.f, S2 = 0.f;
#pragma unroll
            for (int k = 0; k < 16; k++) { S += rs[k]; S2 += rs2[k]; }
            float mean = S * (1.f/512.f);
            float var  = S2 * (1.f/512.f) - mean*mean;
            bmean = mean; brstd = rsqrtf(var + 1e-5f);
        }
        __syncthreads();
        float ln = (t - bmean)*brstd*gv[c] + bv[c];
        x_out[(size_t)bi*CDIM + c] = fmaxf(x[(size_t)bi*CDIM + c] + ln, 0.f);
    }
}

// ------------------------------------------------------------------
extern "C" void kernel_launch(void* const* d_in, const int* in_sizes, int n_in,
                              void* d_out, int out_size)
{
    const float* x    = (const float*)d_in[0];
    const float* edge = (const float*)d_in[1];
    const float* WA   = (const float*)d_in[2];
    const float* WB   = (const float*)d_in[3];
    const float* WE   = (const float*)d_in[4];
    const float* WU   = (const float*)d_in[5];
    const float* WV   = (const float*)d_in[6];
    const float* gv   = (const float*)d_in[7];
    const float* bv   = (const float*)d_in[8];
    const float* ge   = (const float*)d_in[9];
    const float* be   = (const float*)d_in[10];

    float* x_out = (float*)d_out;
    float* e_out = (float*)d_out + (size_t)NROWS_X*CDIM;

    cudaFuncSetAttribute(gemm_all, cudaFuncAttributeMaxDynamicSharedMemorySize, SMEM_GEMM);
    cudaFuncSetAttribute(edge_epilogue, cudaFuncAttributeMaxDynamicSharedMemorySize, EPI_BYTES);

    __half *d_elin, *d_node, *d_eA, *d_xA, *d_WEt, *d_Wct;
    cudaGetSymbolAddress((void**)&d_elin, g_elin);
    cudaGetSymbolAddress((void**)&d_node, g_node);
    cudaGetSymbolAddress((void**)&d_eA, g_eA);
    cudaGetSymbolAddress((void**)&d_xA, g_xA);
    cudaGetSymbolAddress((void**)&d_WEt, g_WEt);
    cudaGetSymbolAddress((void**)&d_Wct, g_Wct);

    prep_all<<<PREP_E_BLKS + PREP_X_BLKS + PREP_W_BLKS, 256>>>(edge, x, WE, WA, WB, WV, WU);

    gemm_all<<<EDGE_CTAS + NODE_CTAS, 256, SMEM_GEMM>>>(
        d_eA, d_WEt, d_xA, d_Wct, d_elin, d_node);

    edge_epilogue<<<BATCH*NNODE, 512, EPI_BYTES>>>(
        x, ge, be, gv, bv, e_out, x_out);
}

// round 16
// speedup vs baseline: 1.2759x; 1.1044x over previous
#include <cuda_runtime.h>
#include <cuda_fp16.h>
#include <cstdint>

#define BATCH 64
#define NNODE 27
#define CDIM  512
#define NNSQ  729
#define NROWS_X (BATCH*NNODE)      // 1728
#define NROWS_E (BATCH*NNSQ)       // 46656
#define SSTR 520

#define BM 128
#define BN 128
#define BK 64
#define SROWB 144                   // smem row stride bytes (64 halves + 16B pad)
#define ARR_BYTES (128*SROWB)       // 18432
#define STAGE_BYTES (2*ARR_BYTES)   // A | B = 36864
#define NSTAGE 2
#define SMEM_GEMM (NSTAGE*STAGE_BYTES)   // 73728 -> 2 CTAs/SM

#define EDGE_CTAS (365*4)           // 1460
#define NODE_CTAS (14*16)           // 224

#define EPI_BYTES ((27*SSTR + 1536) * 4)   // 62304 -> 3 CTAs/SM

// prep kernel block ranges (256 thr each)
#define PREP_E_BLKS (NROWS_E*CDIM/8/256)   // 11664 (2 float4 per thread)
#define PREP_X_BLKS (NROWS_X*CDIM/4/256)   // 864
#define PREP_W_BLKS (16*16*5)              // 1280

// ------------------------------------------------------------------
// scratch (device globals; allocs are forbidden)
// ------------------------------------------------------------------
__device__ __half g_elin[(size_t)NROWS_E*CDIM];         // e_lin fp16
__device__ __half g_node[(size_t)NROWS_X*2048];         // Vix|Vjx|Ujx|XU fp16
__device__ __half g_eA[(size_t)NROWS_E*CDIM];           // edge fp16
__device__ __half g_xA[(size_t)NROWS_X*CDIM];           // x fp16
__device__ __half g_WEt[512*512];                       // WE^T fp16
__device__ __half g_Wct[2048*512];                      // [WA|WB|WV|WU]^T fp16

// ------------------------------------------------------------------
// helpers
// ------------------------------------------------------------------
__device__ __forceinline__ uint32_t smem_to_u32(const void* p) {
    uint32_t a;
    asm("{ .reg .u64 t; cvta.to.shared.u64 t, %1; cvt.u32.u64 %0, t; }" : "=r"(a) : "l"(p));
    return a;
}
__device__ __forceinline__ void cp_async16(uint32_t dst, const void* src, bool pred) {
    int sz = pred ? 16 : 0;
    asm volatile("cp.async.cg.shared.global [%0], [%1], 16, %2;"
                 :: "r"(dst), "l"(src), "r"(sz) : "memory");
}
__device__ __forceinline__ void cp_async16_ca(uint32_t dst, const void* src) {
    asm volatile("cp.async.ca.shared.global [%0], [%1], 16;"
                 :: "r"(dst), "l"(src) : "memory");
}
__device__ __forceinline__ void ldsm4(uint32_t& r0, uint32_t& r1, uint32_t& r2, uint32_t& r3,
                                      uint32_t addr) {
    asm volatile("ldmatrix.sync.aligned.m8n8.x4.shared.b16 {%0,%1,%2,%3}, [%4];"
                 : "=r"(r0), "=r"(r1), "=r"(r2), "=r"(r3) : "r"(addr));
}
__device__ __forceinline__ void mma16816(float* c,
                                         uint32_t a0, uint32_t a1, uint32_t a2, uint32_t a3,
                                         uint32_t b0, uint32_t b1) {
    asm volatile("mma.sync.aligned.m16n8k16.row.col.f32.f16.f16.f32 "
                 "{%0,%1,%2,%3},{%4,%5,%6,%7},{%8,%9},{%0,%1,%2,%3};"
                 : "+f"(c[0]), "+f"(c[1]), "+f"(c[2]), "+f"(c[3])
                 : "r"(a0), "r"(a1), "r"(a2), "r"(a3), "r"(b0), "r"(b1));
}
__device__ __forceinline__ float sigmoid_fast(float x) {
    float t;
    asm("tanh.approx.f32 %0, %1;" : "=f"(t) : "f"(0.5f * x));
    return fmaf(t, 0.5f, 0.5f);
}
__device__ __forceinline__ float exp01(float s) {
    float p = fmaf(s, 0.14285714f, 1.f);
    p = fmaf(p*s, 0.16666667f, 1.f);
    p = fmaf(p*s, 0.2f, 1.f);
    p = fmaf(p*s, 0.25f, 1.f);
    p = fmaf(p*s, 0.33333333f, 1.f);
    p = fmaf(p*s, 0.5f, 1.f);
    return fmaf(p, s, 1.f);
}

// ------------------------------------------------------------------
// K_prep: one launch = edge convert (2xfloat4/thr) | x convert | W^T
// ------------------------------------------------------------------
__global__ void prep_all(const float* __restrict__ edge, const float* __restrict__ x,
                         const float* __restrict__ WE, const float* __restrict__ WA,
                         const float* __restrict__ WB, const float* __restrict__ WV,
                         const float* __restrict__ WU)
{
    int blk = blockIdx.x;
    if (blk < PREP_E_BLKS) {                 // edge: 2 float4 per thread
        int i = (blk*256 + threadIdx.x)*2;
#pragma unroll
        for (int u = 0; u < 2; u++) {
            float4 v = ((const float4*)edge)[i + u];
            ((__half2*)g_eA)[2*(i+u)]   = __floats2half2_rn(v.x, v.y);
            ((__half2*)g_eA)[2*(i+u)+1] = __floats2half2_rn(v.z, v.w);
        }
        return;
    }
    if (blk < PREP_E_BLKS + PREP_X_BLKS) {   // x: 1 float4 per thread
        int i = (blk - PREP_E_BLKS)*256 + threadIdx.x;
        float4 v = ((const float4*)x)[i];
        ((__half2*)g_xA)[2*i]   = __floats2half2_rn(v.x, v.y);
        ((__half2*)g_xA)[2*i+1] = __floats2half2_rn(v.z, v.w);
        return;
    }
    __shared__ float tile[32][33];
    int wblk = blk - PREP_E_BLKS - PREP_X_BLKS;
    int z  = wblk / 256;
    int t2 = wblk % 256;
    int bx = t2 & 15, by = t2 >> 4;
    const float* W = (z == 0) ? WE : (z == 1) ? WA : (z == 2) ? WB : (z == 3) ? WV : WU;
    __half* Oh = (z == 0) ? g_WEt : g_Wct;
    const int nOff = (z == 0) ? 0 : (z - 1) * 512;
    const int k0 = bx * 32, n0 = by * 32;
    const int tx = threadIdx.x & 31, ty = threadIdx.x >> 5;
#pragma unroll
    for (int q = 0; q < 4; q++)
        tile[ty + 8*q][tx] = W[(size_t)(k0 + ty + 8*q)*512 + n0 + tx];
    __syncthreads();
#pragma unroll
    for (int q = 0; q < 4; q++)
        Oh[(size_t)(nOff + n0 + ty + 8*q)*512 + k0 + tx] = __float2half_rn(tile[tx][ty + 8*q]);
}

// ------------------------------------------------------------------
// G: combined fp16 GEMM.  256 thr, 8 warps, warp 32x64,
// CTA 128x128, BK=64, 2-stage, 2 CTAs/SM.  B loads via .ca (L1).
// ------------------------------------------------------------------
__device__ __forceinline__ void load_stage(uint32_t s0, int tid, int row0, int n0, int M, int kt,
    const __half* __restrict__ A, const __half* __restrict__ B)
{
#pragma unroll
    for (int q = 0; q < 4; q++) {
        int idx = tid + q*256;                       // 128 rows x 8 16B-chunks
        int r = idx >> 3, c = idx & 7;
        uint32_t doff = (uint32_t)r*SROWB + (uint32_t)c*16;
        int ar = row0 + r;
        bool av = ar < M;
        size_t agoff = (size_t)(av ? ar : 0)*512 + kt + c*8;
        cp_async16(s0 + doff, A + agoff, av);
        size_t bgoff = (size_t)(n0 + r)*512 + kt + c*8;
        cp_async16_ca(s0 + ARR_BYTES + doff, B + bgoff);   // weights: L1-cached
    }
    asm volatile("cp.async.commit_group;" ::: "memory");
}

__device__ __forceinline__ void compute_stage(uint32_t s0, int lane, int wm, int wn,
                                              float acc[2][8][4])
{
#pragma unroll
    for (int s = 0; s < 4; s++) {
        uint32_t a[2][4];
#pragma unroll
        for (int f = 0; f < 2; f++) {
            uint32_t ra = s0 + (uint32_t)(wm*32 + f*16 + (lane & 15))*SROWB
                             + (uint32_t)((lane >> 4)*16 + s*32);
            ldsm4(a[f][0], a[f][1], a[f][2], a[f][3], ra);
        }
#pragma unroll
        for (int h = 0; h < 2; h++) {
            uint32_t bh[2][4];
#pragma unroll
            for (int q = 0; q < 2; q++) {
                uint32_t rb = s0 + ARR_BYTES
                    + (uint32_t)(wn*64 + h*32 + q*16 + (lane & 15))*SROWB
                    + (uint32_t)((lane >> 4)*16 + s*32);
                ldsm4(bh[q][0], bh[q][1], bh[q][2], bh[q][3], rb);
            }
#pragma unroll
            for (int f = 0; f < 2; f++)
#pragma unroll
                for (int q = 0; q < 2; q++) {
                    int j = h*4 + q*2;
                    mma16816(acc[f][j],   a[f][0], a[f][1], a[f][2], a[f][3], bh[q][0], bh[q][2]);
                    mma16816(acc[f][j+1], a[f][0], a[f][1], a[f][2], a[f][3], bh[q][1], bh[q][3]);
                }
        }
    }
}

__global__ __launch_bounds__(256, 2)
void gemm_all(const __half* __restrict__ eA, const __half* __restrict__ WEt,
              const __half* __restrict__ xA, const __half* __restrict__ Wct,
              __half* __restrict__ Ce, __half* __restrict__ Cn)
{
    extern __shared__ char smem[];
    const uint32_t sb = smem_to_u32(smem);
    const int tid = threadIdx.x;
    const int lane = tid & 31, wid = tid >> 5;
    const int wm = wid >> 1, wn = wid & 1;

    const bool isEdge = blockIdx.x < EDGE_CTAS;
    const __half *A, *B;
    __half* C; int M, ldC, row0, n0;
    if (isEdge) {
        int bx = blockIdx.x % 365, by = blockIdx.x / 365;
        A = eA; B = WEt; C = Ce; M = NROWS_E; ldC = 512;
        row0 = bx * BM; n0 = by * BN;
    } else {
        int c2 = blockIdx.x - EDGE_CTAS;
        int bx = c2 % 14, by = c2 / 14;
        A = xA; B = Wct; C = Cn; M = NROWS_X; ldC = 2048;
        row0 = bx * BM; n0 = by * BN;
    }

    float acc[2][8][4];
#pragma unroll
    for (int f = 0; f < 2; f++)
#pragma unroll
        for (int j = 0; j < 8; j++)
#pragma unroll
            for (int v = 0; v < 4; v++) acc[f][j][v] = 0.f;

    load_stage(sb, tid, row0, n0, M, 0, A, B);

    const int NT = 512 / BK;   // 8
    for (int t = 0; t < NT; t++) {
        asm volatile("cp.async.wait_group 0;" ::: "memory");
        __syncthreads();
        if (t + 1 < NT)
            load_stage(sb + ((t+1) & 1)*STAGE_BYTES, tid, row0, n0, M, (t+1)*BK, A, B);
        compute_stage(sb + (t & 1)*STAGE_BYTES, lane, wm, wn, acc);
    }

    // epilogue: fp16 stores (both branches)
#pragma unroll
    for (int f = 0; f < 2; f++) {
        int rbase = row0 + wm*32 + f*16 + (lane >> 2);
#pragma unroll
        for (int h = 0; h < 2; h++) {
            int r = rbase + h*8;
            if (r < M) {
                __half* dst = C + (size_t)r*ldC + n0 + wn*64 + (lane & 3)*2;
#pragma unroll
                for (int j = 0; j < 8; j++)
                    *(__half2*)&dst[j*8] = __floats2half2_rn(acc[f][j][2*h], acc[f][j][2*h+1]);
            }
        }
    }
}

// ------------------------------------------------------------------
// K_epi: per (b,i) CTA, 512 threads, 62.3 KB smem (3 CTAs/SM).
// 16B-vectorized global accesses throughout Phase A / staging.
// ------------------------------------------------------------------
__global__ __launch_bounds__(512)
void edge_epilogue(const float* __restrict__ x,
                   const float* __restrict__ ge, const float* __restrict__ be,
                   const float* __restrict__ gv, const float* __restrict__ bv,
                   float* __restrict__ edge_out, float* __restrict__ x_out)
{
    extern __shared__ float sm[];
    float* sS   = sm;                 // [27][520]
    float* sVix = sm + 27*SSTR;
    float* sGe  = sVix + 512;
    float* sBe  = sGe + 512;
    __shared__ float rs[16], rs2[16];
    __shared__ float bmean, brstd;

    const int tid = threadIdx.x;
    const int bi  = blockIdx.x;
    const int b   = bi / NNODE;
    const int i   = bi % NNODE;
    const size_t rowBaseE = (size_t)b*NNSQ + (size_t)i*NNODE;
    const __half* eBase  = g_eA + rowBaseE*CDIM;
    const __half* elBase = g_elin + rowBaseE*CDIM;

    {   // Vix / gamma / beta
        const __half* vix = g_node + (size_t)bi*2048;
        sVix[tid] = __half2float(vix[tid]);
        sGe[tid]  = ge[tid];
        sBe[tid]  = be[tid];
    }
    // load e_lin tile 27x512 fp16 -> sS fp32, 16B global loads
#pragma unroll
    for (int l = 0; l < 4; l++) {
        int idx = tid + l*512;
        if (idx < 27*64) {
            int r = idx >> 6, c8 = idx & 63;
            uint4 raw = *(const uint4*)(elBase + (size_t)r*512 + c8*8);   // 8 halves
            float2 f0 = __half22float2(*(__half2*)&raw.x);
            float2 f1 = __half22float2(*(__half2*)&raw.y);
            float2 f2 = __half22float2(*(__half2*)&raw.z);
            float2 f3 = __half22float2(*(__half2*)&raw.w);
            float* d = &sS[r*SSTR + c8*8];
            float4 o0 = {f0.x, f0.y, f1.x, f1.y};
            float4 o1 = {f2.x, f2.y, f3.x, f3.y};
            *(float4*)&d[0] = o0;
            *(float4*)&d[4] = o1;
        }
    }
    __syncthreads();

    // Phase A: rows (16 warps over 27 rows), 4 cols/thread vectors
    const int lane = tid & 31, wrp = tid >> 5;
    for (int r = wrp; r < NNODE; r += 16) {
        const __half* vjx = g_node + ((size_t)b*NNODE + r)*2048 + 512;  // Vjx fp16
        float4 v[4]; float s = 0.f, s2 = 0.f;
#pragma unroll
        for (int u = 0; u < 4; u++) {
            int c4 = lane + u*32;                    // float4 index 0..127
            float4 t = *(float4*)&sS[r*SSTR + 4*c4];
            float4 vi = *(const float4*)&sVix[4*c4];
            uint2 vjr = *(const uint2*)&vjx[4*c4];   // 4 halves
            float2 vj0 = __half22float2(*(__half2*)&vjr.x);
            float2 vj1 = __half22float2(*(__half2*)&vjr.y);
            t.x += vi.x + vj0.x; t.y += vi.y + vj0.y;
            t.z += vi.z + vj1.x; t.w += vi.w + vj1.y;
            v[u] = t;
            s += (t.x + t.y) + (t.z + t.w);
            s2 += (t.x*t.x + t.y*t.y) + (t.z*t.z + t.w*t.w);
        }
#pragma unroll
        for (int o = 16; o > 0; o >>= 1) {
            s  += __shfl_xor_sync(0xffffffffu, s,  o);
            s2 += __shfl_xor_sync(0xffffffffu, s2, o);
        }
        float mean = s * (1.f/512.f);
        float var  = s2 * (1.f/512.f) - mean*mean;
        float rstd = rsqrtf(var + 1e-5f);
        const __half* eRow = eBase + (size_t)r*CDIM;
        float* oRow = edge_out + (rowBaseE + r)*CDIM;
#pragma unroll
        for (int u = 0; u < 4; u++) {
            int c4 = lane + u*32;
            float4 g = *(const float4*)&sGe[4*c4];
            float4 bb = *(const float4*)&sBe[4*c4];
            uint2 er = *(const uint2*)&eRow[4*c4];
            float2 e0 = __half22float2(*(__half2*)&er.x);
            float2 e1 = __half22float2(*(__half2*)&er.y);
            float ln0 = (v[u].x - mean)*rstd*g.x + bb.x;
            float ln1 = (v[u].y - mean)*rstd*g.y + bb.y;
            float ln2 = (v[u].z - mean)*rstd*g.z + bb.z;
            float ln3 = (v[u].w - mean)*rstd*g.w + bb.w;
            float4 eo = { e0.x + fmaxf(ln0, 0.f), e0.y + fmaxf(ln1, 0.f),
                          e1.x + fmaxf(ln2, 0.f), e1.y + fmaxf(ln3, 0.f) };
            *(float4*)&oRow[4*c4] = eo;
            float4 sg = { sigmoid_fast(eo.x), sigmoid_fast(eo.y),
                          sigmoid_fast(eo.z), sigmoid_fast(eo.w) };
            *(float4*)&sS[r*SSTR + 4*c4] = sg;
        }
    }
    __syncthreads();

    // Phase B: one column per thread — softmax over j + gated aggregation
    const int c = tid;
    float aggv;
    {
        float sum = 0.f, a = 0.f;
#pragma unroll
        for (int j = 0; j < NNODE; j++) {
            float ex = exp01(sS[j*SSTR + c]);
            sum += ex;
            a   += ex * __half2float(g_node[((size_t)b*NNODE + j)*2048 + 1024 + c]);  // Ujx
        }
        aggv = a / (sum * (float)NNODE);
    }

    // Phase C (fused node finalize for row bi)
    {
        float t = __half2float(g_node[(size_t)bi*2048 + 1536 + c]) + aggv;   // XU + agg
        float s = t, s2 = t*t;
#pragma unroll
        for (int o = 16; o > 0; o >>= 1) {
            s  += __shfl_xor_sync(0xffffffffu, s,  o);
            s2 += __shfl_xor_sync(0xffffffffu, s2, o);
        }
        if (lane == 0) { rs[wrp] = s; rs2[wrp] = s2; }
        __syncthreads();
        if (tid == 0) {
            float S = 0.f, S2 = 0.f;
#pragma unroll
            for (int k = 0; k < 16; k++) { S += rs[k]; S2 += rs2[k]; }
            float mean = S * (1.f/512.f);
            float var  = S2 * (1.f/512.f) - mean*mean;
            bmean = mean; brstd = rsqrtf(var + 1e-5f);
        }
        __syncthreads();
        float ln = (t - bmean)*brstd*gv[c] + bv[c];
        x_out[(size_t)bi*CDIM + c] = fmaxf(x[(size_t)bi*CDIM + c] + ln, 0.f);
    }
}

// ------------------------------------------------------------------
extern "C" void kernel_launch(void* const* d_in, const int* in_sizes, int n_in,
                              void* d_out, int out_size)
{
    const float* x    = (const float*)d_in[0];
    const float* edge = (const float*)d_in[1];
    const float* WA   = (const float*)d_in[2];
    const float* WB   = (const float*)d_in[3];
    const float* WE   = (const float*)d_in[4];
    const float* WU   = (const float*)d_in[5];
    const float* WV   = (const float*)d_in[6];
    const float* gv   = (const float*)d_in[7];
    const float* bv   = (const float*)d_in[8];
    const float* ge   = (const float*)d_in[9];
    const float* be   = (const float*)d_in[10];

    float* x_out = (float*)d_out;
    float* e_out = (float*)d_out + (size_t)NROWS_X*CDIM;

    cudaFuncSetAttribute(gemm_all, cudaFuncAttributeMaxDynamicSharedMemorySize, SMEM_GEMM);
    cudaFuncSetAttribute(edge_epilogue, cudaFuncAttributeMaxDynamicSharedMemorySize, EPI_BYTES);

    __half *d_elin, *d_node, *d_eA, *d_xA, *d_WEt, *d_Wct;
    cudaGetSymbolAddress((void**)&d_elin, g_elin);
    cudaGetSymbolAddress((void**)&d_node, g_node);
    cudaGetSymbolAddress((void**)&d_eA, g_eA);
    cudaGetSymbolAddress((void**)&d_xA, g_xA);
    cudaGetSymbolAddress((void**)&d_WEt, g_WEt);
    cudaGetSymbolAddress((void**)&d_Wct, g_Wct);

    prep_all<<<PREP_E_BLKS + PREP_X_BLKS + PREP_W_BLKS, 256>>>(edge, x, WE, WA, WB, WV, WU);

    gemm_all<<<EDGE_CTAS + NODE_CTAS, 256, SMEM_GEMM>>>(
        d_eA, d_WEt, d_xA, d_Wct, d_elin, d_node);

    edge_epilogue<<<BATCH*NNODE, 512, EPI_BYTES>>>(
        x, ge, be, gv, bv, e_out, x_out);
}